// round 5
// baseline (speedup 1.0000x reference)
#include <cuda_runtime.h>
#include <cuda_fp16.h>
#include <cstdint>
#include <cstddef>

#define MDIM 16
#define KDIM 8192
#define NDIM 8192
#define KSPLIT 8
#define NT 128                 // n tiles of 64
#define THREADS 256
#define NGRP 8                 // groups (128 k) per k-split
#define NBLK 8                 // k16-blocks per group

// x fragments in virtual-k order: [512 kblocks][32 lanes][hi,lo] x 16B
__device__ __align__(16) uint4 g_xfrag[512][32][2];          // 512 KB
__device__ __align__(16) float g_partial[KSPLIT][1024][128]; // [ks][n8blk][m*8+nc], 4 MB

__device__ __forceinline__ void mma16816(float& c0, float& c1, float& c2, float& c3,
                                         uint32_t a0, uint32_t a1, uint32_t a2, uint32_t a3,
                                         uint32_t b0, uint32_t b1) {
    asm volatile(
        "mma.sync.aligned.m16n8k16.row.col.f32.f16.f16.f32 "
        "{%0,%1,%2,%3},{%4,%5,%6,%7},{%8,%9},{%0,%1,%2,%3};"
        : "+f"(c0), "+f"(c1), "+f"(c2), "+f"(c3)
        : "r"(a0), "r"(a1), "r"(a2), "r"(a3), "r"(b0), "r"(b1));
}

// one int32 (8 nibbles) -> half2 {q[c], q[c+4]} * s + z   (bias removed exactly)
__device__ __forceinline__ uint32_t dq2(uint32_t w, uint32_t c4, __half2 s2, __half2 z2) {
    uint32_t t = ((w >> c4) & 0x000F000Fu) | 0x64006400u;
    uint32_t bu = 0x64006400u;
    __half2 q = __hsub2(*reinterpret_cast<__half2*>(&t), *reinterpret_cast<__half2*>(&bu));
    __half2 r = __hfma2(q, s2, z2);
    return *reinterpret_cast<uint32_t*>(&r);
}

// Pack x (fp32 [16][8192]) into hi/lo f16 A-fragments, virtual-k order.
// virtual k 2c   <-> actual kb + c
// virtual k 2c+1 <-> actual kb + c + 4      (c = lane&3, kb = 16*block)
__global__ void __launch_bounds__(THREADS) xprep(const float* __restrict__ x) {
    int t = blockIdx.x * THREADS + threadIdx.x;   // 0..16383
    int b = t >> 5, l = t & 31;
    int r = l >> 2, c = l & 3, kb = b * 16;
    const float* x0 = x + (size_t)r * KDIM;
    const float* x1 = x + (size_t)(r + 8) * KDIM;
    float f[8];
    f[0] = x0[kb + c];      f[1] = x0[kb + c + 4];       // a0: row r,  k-lo
    f[2] = x1[kb + c];      f[3] = x1[kb + c + 4];       // a1: row r+8,k-lo
    f[4] = x0[kb + 8 + c];  f[5] = x0[kb + 12 + c];      // a2: row r,  k-hi
    f[6] = x1[kb + 8 + c];  f[7] = x1[kb + 12 + c];      // a3: row r+8,k-hi
    uint4 hi, lo;
    uint32_t* hp = reinterpret_cast<uint32_t*>(&hi);
    uint32_t* lp = reinterpret_cast<uint32_t*>(&lo);
#pragma unroll
    for (int i = 0; i < 4; i++) {
        __half h0 = __float2half_rn(f[2 * i]);
        __half h1 = __float2half_rn(f[2 * i + 1]);
        __half e0 = __float2half_rn(f[2 * i] - __half2float(h0));
        __half e1 = __float2half_rn(f[2 * i + 1] - __half2float(h1));
        __half2 h2 = __halves2half2(h0, h1);
        __half2 e2 = __halves2half2(e0, e1);
        hp[i] = *reinterpret_cast<uint32_t*>(&h2);
        lp[i] = *reinterpret_cast<uint32_t*>(&e2);
    }
    g_xfrag[b][l][0] = hi;
    g_xfrag[b][l][1] = lo;
}

__global__ void __launch_bounds__(THREADS) wq_gemm(const int* __restrict__ qw,
                                                   const float* __restrict__ scales,
                                                   const float* __restrict__ zeros) {
    const int tid = threadIdx.x;
    const int wid = tid >> 5, lane = tid & 31;
    const int nt = blockIdx.x & (NT - 1);
    const int ks = blockIdx.x >> 7;
    const int nblk = nt * 8 + wid;            // n8 block 0..1023
    const int row = nblk * 8 + (lane >> 2);   // n
    const uint32_t c4 = (uint32_t)(lane & 3) * 4;

    // qweight: per group, this lane's row needs 16 consecutive int32 (64B) = 4x LDG.128
    const uint4* qp = reinterpret_cast<const uint4*>(qw + (size_t)row * (KDIM / 8) + ks * 128);
    const float* sp = scales + (size_t)(ks * NGRP) * NDIM + row;
    const float* zp = zeros + (size_t)(ks * NGRP) * NDIM + row;

    float c0 = 0.f, c1 = 0.f, c2 = 0.f, c3 = 0.f;

#pragma unroll 1
    for (int g = 0; g < NGRP; g++) {
        float sf = sp[(size_t)g * NDIM];
        float zf = zp[(size_t)g * NDIM];
        uint4 qa0 = qp[g * 4 + 0];
        uint4 qa1 = qp[g * 4 + 1];
        uint4 qa2 = qp[g * 4 + 2];
        uint4 qa3 = qp[g * 4 + 3];
        __half hs = __float2half_rn(sf), hz = __float2half_rn(zf);
        __half2 s2 = __half2half2(hs), z2 = __half2half2(hz);

        const uint4* xf = &g_xfrag[ks * 64 + g * 8][lane][0];
        uint32_t wlist[16];
        wlist[0] = qa0.x; wlist[1] = qa0.y; wlist[2] = qa0.z; wlist[3] = qa0.w;
        wlist[4] = qa1.x; wlist[5] = qa1.y; wlist[6] = qa1.z; wlist[7] = qa1.w;
        wlist[8] = qa2.x; wlist[9] = qa2.y; wlist[10] = qa2.z; wlist[11] = qa2.w;
        wlist[12] = qa3.x; wlist[13] = qa3.y; wlist[14] = qa3.z; wlist[15] = qa3.w;

#pragma unroll
        for (int b = 0; b < NBLK; b++) {
            uint4 ah = xf[(size_t)b * 64];      // g_xfrag[blk+b][lane][0]
            uint4 al = xf[(size_t)b * 64 + 1];  // g_xfrag[blk+b][lane][1]
            uint32_t b0 = dq2(wlist[2 * b], c4, s2, z2);
            uint32_t b1 = dq2(wlist[2 * b + 1], c4, s2, z2);
            mma16816(c0, c1, c2, c3, ah.x, ah.y, ah.z, ah.w, b0, b1);
            mma16816(c0, c1, c2, c3, al.x, al.y, al.z, al.w, b0, b1);
        }
    }

    // D fragment: rows (lane>>2) and +8, cols 2*(lane&3), +1
    float* pb = &g_partial[ks][nblk][0];
    int off = (lane >> 2) * 8 + (lane & 3) * 2;
    *reinterpret_cast<float2*>(pb + off) = make_float2(c0, c1);
    *reinterpret_cast<float2*>(pb + 64 + off) = make_float2(c2, c3);
}

__global__ void __launch_bounds__(THREADS) wq_combine(const float* __restrict__ bias,
                                                      float* __restrict__ out) {
    int idx = blockIdx.x * THREADS + threadIdx.x;  // 0..131071
    int m = idx >> 13;
    int n = idx & (NDIM - 1);
    float acc = bias[n];
    int pofs = m * 8 + (n & 7);
    int nb = n >> 3;
#pragma unroll
    for (int ks = 0; ks < KSPLIT; ks++) acc += g_partial[ks][nb][pofs];
    out[idx] = acc;
}

extern "C" void kernel_launch(void* const* d_in, const int* in_sizes, int n_in,
                              void* d_out, int out_size) {
    const float* x = (const float*)d_in[0];
    const int* qw = (const int*)d_in[1];
    const float* sc = (const float*)d_in[2];
    const float* zz = (const float*)d_in[3];
    const float* bias = (const float*)d_in[4];
    (void)in_sizes; (void)n_in; (void)out_size;

    xprep<<<64, THREADS>>>(x);
    wq_gemm<<<NT * KSPLIT, THREADS>>>(qw, sc, zz);
    wq_combine<<<(MDIM * NDIM) / THREADS, THREADS>>>(bias, (float*)d_out);
}

// round 7
// speedup vs baseline: 2.1391x; 2.1391x over previous
#include <cuda_runtime.h>
#include <cuda_fp16.h>
#include <cstdint>
#include <cstddef>

#define MDIM 16
#define KDIM 8192
#define NDIM 8192
#define KSPLIT 16
#define KPER 512               // k per split
#define NGRP 4                 // 128-k groups per split
#define NT 16                  // n tiles (512 n each)
#define THREADS 256
#define N8_PER_WARP 8

// smem: raw x [16][516] floats, then frags [32 blocks][32 lanes] uint4
#define RAW_ROW 516
#define SM_FRAG_OFF 33024      // 16*516*4, 16B aligned
#define SM_TOTAL (33024 + 32 * 32 * 16)   // 49408 B

__device__ __align__(16) float g_partial[KSPLIT][1024][128];   // 8 MB

__device__ __forceinline__ void mma16816(float4& c,
                                         uint32_t a0, uint32_t a1, uint32_t a2, uint32_t a3,
                                         uint32_t b0, uint32_t b1) {
    asm volatile(
        "mma.sync.aligned.m16n8k16.row.col.f32.f16.f16.f32 "
        "{%0,%1,%2,%3},{%4,%5,%6,%7},{%8,%9},{%0,%1,%2,%3};"
        : "+f"(c.x), "+f"(c.y), "+f"(c.z), "+f"(c.w)
        : "r"(a0), "r"(a1), "r"(a2), "r"(a3), "r"(b0), "r"(b1));
}

// one int32 (8 nibbles) -> half2 {q[c], q[c+4]} * s + z  (bias removed exactly)
__device__ __forceinline__ uint32_t dq2(uint32_t w, uint32_t c4, __half2 s2, __half2 z2) {
    uint32_t t = ((w >> c4) & 0x000F000Fu) | 0x64006400u;
    uint32_t bu = 0x64006400u;
    __half2 q = __hsub2(*reinterpret_cast<__half2*>(&t), *reinterpret_cast<__half2*>(&bu));
    __half2 r = __hfma2(q, s2, z2);
    return *reinterpret_cast<uint32_t*>(&r);
}

__global__ void __launch_bounds__(THREADS, 2) wq_gemm(
    const float* __restrict__ x, const int* __restrict__ qw,
    const float* __restrict__ scales, const float* __restrict__ zeros) {
    extern __shared__ char smem[];
    float* xraw = reinterpret_cast<float*>(smem);
    uint4* frag = reinterpret_cast<uint4*>(smem + SM_FRAG_OFF);
    const int tid = threadIdx.x;
    const int nt = blockIdx.x & (NT - 1);
    const int ks = blockIdx.x >> 4;

    // ---- phase 1: coalesced raw x chunk [16][512] -> smem (padded rows) ----
    const float* xg = x + ks * KPER;
#pragma unroll
    for (int i = 0; i < 8; i++) {
        int e = tid + i * THREADS;          // 0..2047 float4 slots
        int r = e >> 7;                     // 128 float4 per row
        int kk = (e & 127) << 2;
        float4 v = *reinterpret_cast<const float4*>(xg + (size_t)r * KDIM + kk);
        *reinterpret_cast<float4*>(xraw + r * RAW_ROW + kk) = v;
    }
    __syncthreads();

    // ---- phase 2: pack A-fragments (virtual-k permutation: 2c<->c, 2c+1<->c+4) ----
#pragma unroll
    for (int j = 0; j < 4; j++) {
        int e = tid + j * THREADS;          // 0..1023 = (block, lane)
        int b = e >> 5, l = e & 31;
        int r = l >> 2, c = l & 3, kb = b * 16;
        const float* r0 = xraw + r * RAW_ROW + kb;
        const float* r1 = xraw + (r + 8) * RAW_ROW + kb;
        __half2 a0 = __floats2half2_rn(r0[c], r0[c + 4]);
        __half2 a1 = __floats2half2_rn(r1[c], r1[c + 4]);
        __half2 a2 = __floats2half2_rn(r0[8 + c], r0[12 + c]);
        __half2 a3 = __floats2half2_rn(r1[8 + c], r1[12 + c]);
        uint4 f;
        f.x = *reinterpret_cast<uint32_t*>(&a0);
        f.y = *reinterpret_cast<uint32_t*>(&a1);
        f.z = *reinterpret_cast<uint32_t*>(&a2);
        f.w = *reinterpret_cast<uint32_t*>(&a3);
        frag[e] = f;
    }
    __syncthreads();

    // ---- main loop ----
    const int wid = tid >> 5, lane = tid & 31;
    const int nb0 = nt * 64 + wid * N8_PER_WARP;   // first n8-block of this warp
    const int r_in8 = lane >> 2;
    const uint32_t c4 = (uint32_t)(lane & 3) * 4;
    const int row0 = nb0 * 8 + r_in8;

    // qweight as uint4: row stride 256; ksplit offset = 512k = 64 int32 = 16 uint4
    const uint4* qp = reinterpret_cast<const uint4*>(qw) + (size_t)row0 * 256 + ks * 16;

    float4 acc[N8_PER_WARP];
#pragma unroll
    for (int i = 0; i < N8_PER_WARP; i++) acc[i] = make_float4(0.f, 0.f, 0.f, 0.f);

#pragma unroll 1
    for (int g = 0; g < NGRP; g++) {
        __half2 s2[N8_PER_WARP], z2[N8_PER_WARP];
        const float* sp = scales + (size_t)(ks * NGRP + g) * NDIM + row0;
        const float* zp = zeros + (size_t)(ks * NGRP + g) * NDIM + row0;
#pragma unroll
        for (int i = 0; i < N8_PER_WARP; i++) {
            s2[i] = __half2half2(__float2half_rn(sp[i * 8]));
            z2[i] = __half2half2(__float2half_rn(zp[i * 8]));
        }
#pragma unroll
        for (int p = 0; p < 4; p++) {       // 4 uint4 = 8 k16-blocks per group-row
            uint4 wq[N8_PER_WARP];
#pragma unroll
            for (int i = 0; i < N8_PER_WARP; i++)
                wq[i] = qp[(size_t)i * 2048 + g * 4 + p];
#pragma unroll
            for (int sub = 0; sub < 2; sub++) {
                uint4 ah = frag[((g * 8 + p * 2 + sub) << 5) + lane];
#pragma unroll
                for (int i = 0; i < N8_PER_WARP; i++) {
                    uint32_t w0 = sub ? wq[i].z : wq[i].x;
                    uint32_t w1 = sub ? wq[i].w : wq[i].y;
                    uint32_t b0 = dq2(w0, c4, s2[i], z2[i]);
                    uint32_t b1 = dq2(w1, c4, s2[i], z2[i]);
                    mma16816(acc[i], ah.x, ah.y, ah.z, ah.w, b0, b1);
                }
            }
        }
    }

    // ---- store partials ----
    const int off = r_in8 * 8 + (lane & 3) * 2;
#pragma unroll
    for (int i = 0; i < N8_PER_WARP; i++) {
        float* pb = &g_partial[ks][nb0 + i][0];
        *reinterpret_cast<float2*>(pb + off) = make_float2(acc[i].x, acc[i].y);
        *reinterpret_cast<float2*>(pb + 64 + off) = make_float2(acc[i].z, acc[i].w);
    }
}

__global__ void __launch_bounds__(256) wq_combine(const float* __restrict__ bias,
                                                  float* __restrict__ out) {
    int idx = blockIdx.x * 256 + threadIdx.x;   // 0..131071
    int m = idx >> 13;
    int n = idx & (NDIM - 1);
    float acc = bias[n];
    int nb = n >> 3;
    int off = m * 8 + (n & 7);
#pragma unroll
    for (int ks = 0; ks < KSPLIT; ks++) acc += g_partial[ks][nb][off];
    out[idx] = acc;
}

extern "C" void kernel_launch(void* const* d_in, const int* in_sizes, int n_in,
                              void* d_out, int out_size) {
    const float* x = (const float*)d_in[0];
    const int* qw = (const int*)d_in[1];
    const float* sc = (const float*)d_in[2];
    const float* zz = (const float*)d_in[3];
    const float* bias = (const float*)d_in[4];
    (void)in_sizes; (void)n_in; (void)out_size;

    cudaFuncSetAttribute(wq_gemm, cudaFuncAttributeMaxDynamicSharedMemorySize, SM_TOTAL);
    wq_gemm<<<NT * KSPLIT, THREADS, SM_TOTAL>>>(x, qw, sc, zz);
    wq_combine<<<(MDIM * NDIM) / 256, 256>>>(bias, (float*)d_out);
}